// round 13
// baseline (speedup 1.0000x reference)
#include <cuda_runtime.h>
#include <cstdint>

#define BS   64
#define LEN  128
#define CN   32
#define HID  256
#define NROW (BS*CN)          // 2048 sequence rows
#define OUT1 (NROW*HID)       // 524288 output elements per copy
#define EV_CAP 1536           // per-row spike-event capacity (expect ~17)

// Scratch (static __device__ arrays: allocation-free)
__device__ float4 g_coef[HID];        // folded conv+BN coefficients
__device__ float  g_wt[HID*HID];      // Wt[o*256+j] = lin_w[j*256+o]

// ---------------------------------------------------------------------------
// prep: coalesced 32x32 tile transpose of lin_w + conv/BN coefficient fold.
// grid = 64 (8x8 tiles), block = 256 (32x8).
// ---------------------------------------------------------------------------
__global__ void prep_kernel(const float* __restrict__ conv_w,
                            const float* __restrict__ conv_b,
                            const float* __restrict__ bn_gamma,
                            const float* __restrict__ bn_beta,
                            const float* __restrict__ bn_mean,
                            const float* __restrict__ bn_var,
                            const float* __restrict__ lin_w) {
    __shared__ float tile[32][33];
    int bx = blockIdx.x & 7;         // o-tile
    int by = blockIdx.x >> 3;        // j-tile
    int tx = threadIdx.x & 31;
    int ty = threadIdx.x >> 5;       // 0..7

    #pragma unroll
    for (int k = 0; k < 4; ++k) {
        int lj = ty + k * 8;
        tile[lj][tx] = lin_w[(by*32 + lj) * HID + bx*32 + tx];   // coalesced read
    }
    __syncthreads();
    #pragma unroll
    for (int k = 0; k < 4; ++k) {
        int lo = ty + k * 8;
        g_wt[(bx*32 + lo) * HID + by*32 + tx] = tile[tx][lo];    // coalesced write
    }

    if (blockIdx.x == 0) {
        int j = threadIdx.x;         // 0..255
        float inv = bn_gamma[j] / sqrtf(bn_var[j] + 1e-5f);
        float4 cf;
        cf.x = conv_w[j*3 + 0] * inv;
        cf.y = conv_w[j*3 + 1] * inv;
        cf.z = conv_w[j*3 + 2] * inv;
        cf.w = (conv_b[j] - bn_mean[j]) * inv + bn_beta[j];
        g_coef[j] = cf;
    }
}

// ---------------------------------------------------------------------------
// fused encoder + event-driven RNN. grid = NROW (2048), block = 128.
// Phase A: thread l scans LIF over 256 hidden channels for position (b,c,l),
//          masks -> smem.
// Phase B: cooperative build of a time-ordered spike-event list (t,o).
// Phase C: each thread owns neurons j=tid and j=tid+128; skip zero-input
//          steps via exact power-of-2 decay; LIF update only at event steps.
//          Dense fallback if bias != 0 or event overflow.
// ---------------------------------------------------------------------------
__global__ __launch_bounds__(128) void fused_kernel(const float* __restrict__ x,
                                                    const float* __restrict__ lin_b,
                                                    float* __restrict__ out, int ncopy) {
    __shared__ float4   scoef[HID];        // 4KB
    __shared__ unsigned smask[LEN*8];      // 4KB: word i = t*8+w
    __shared__ unsigned sev[EV_CAP];       // 6KB: (t<<8)|o, ordered (t asc, o asc)
    __shared__ int      swcnt[5];

    const int tid  = threadIdx.x;
    const int lane = tid & 31;
    const int wid  = tid >> 5;
    const int n    = blockIdx.x;
    const int b    = n >> 5;
    const int c    = n & 31;

    scoef[tid]       = g_coef[tid];
    scoef[tid + 128] = g_coef[tid + 128];
    float bias0 = lin_b[tid];
    float bias1 = lin_b[tid + 128];
    int anybias = __syncthreads_or(bias0 != 0.0f || bias1 != 0.0f);  // also barriers scoef

    // ---- Phase A: encoder LIF scan over hidden axis (exact arithmetic) ----
    {
        const int l = tid;                       // 0..127
        const int g = b * 4096 + l * 32 + c;     // x flat index (bs, len, c)
        float x0 = x[g];
        float xm = (l > 0)   ? x[g - 32] : 0.0f;
        float xp = (l < 127) ? x[g + 32] : 0.0f;

        float v = 0.0f;
        for (int w = 0; w < 8; ++w) {
            unsigned m = 0;
            #pragma unroll
            for (int bit = 0; bit < 32; ++bit) {
                float4 cf = scoef[w*32 + bit];
                float enc = cf.w;
                enc = fmaf(cf.x, xm, enc);
                enc = fmaf(cf.y, x0, enc);
                enc = fmaf(cf.z, xp, enc);
                v = fmaf(enc - v, 0.5f, v);                       // v += (enc-v)/2
                if (v >= 1.0f) { m |= (1u << bit); v = 0.0f; }    // spike + reset
            }
            smask[l*8 + w] = m;
        }
    }
    __syncthreads();

    // ---- Phase B: build ordered event list (4 warps, 256 words each) ----
    int cnt = 0;
    #pragma unroll
    for (int k = 0; k < 8; ++k)
        cnt += __popc(smask[wid*256 + k*32 + lane]);
    #pragma unroll
    for (int o = 16; o; o >>= 1) cnt += __shfl_down_sync(~0u, cnt, o);
    if (lane == 0) swcnt[wid] = cnt;
    __syncthreads();
    if (tid == 0) {
        int s = 0;
        #pragma unroll
        for (int w = 0; w < 4; ++w) { int t = swcnt[w]; swcnt[w] = s; s += t; }
        swcnt[4] = s;
    }
    __syncthreads();
    const int nev = swcnt[4];
    const bool dense = anybias || (nev > EV_CAP);

    if (!dense) {
        int base = swcnt[wid];
        #pragma unroll
        for (int k = 0; k < 8; ++k) {
            int wi = wid*256 + k*32 + lane;          // word index = t*8 + w
            unsigned word = smask[wi];
            int pc = __popc(word);
            int off = pc;                            // inclusive scan
            #pragma unroll
            for (int o = 1; o < 32; o <<= 1) {
                int t = __shfl_up_sync(~0u, off, o);
                if (lane >= o) off += t;
            }
            int pos = base + off - pc;
            int t  = wi >> 3;
            int wq = wi & 7;
            while (word) {
                int bit = __ffs(word) - 1; word &= word - 1;
                sev[pos++] = (unsigned)((t << 8) | (wq*32 + bit));
            }
            base += __shfl_sync(~0u, off, 31);
        }
    }
    __syncthreads();

    // ---- Phase C: RNN over time ----
    float out0 = 0.0f, out1 = 0.0f;

    if (!dense) {
        float v0 = 0.0f, v1 = 0.0f;
        int cur = -1;
        int e = 0;
        while (e < nev) {
            unsigned ev = sev[e];
            int t = (int)(ev >> 8);
            int gap = t - cur - 1;                       // decay-only steps
            float sc = __int_as_float((127 - gap) << 23); // exact 2^-gap
            v0 *= sc; v1 *= sc;
            float z0 = 0.0f, z1 = 0.0f;
            do {                                          // gather column sums, o asc
                int o = (int)(ev & 255);
                const float* wr = g_wt + o * HID;
                z0 += wr[tid];
                z1 += wr[tid + 128];
                ++e;
                if (e >= nev) break;
                ev = sev[e];
            } while ((int)(ev >> 8) == t);
            float nv0 = fmaf(z0 - v0, 0.5f, v0);
            float nv1 = fmaf(z1 - v1, 0.5f, v1);
            bool s0 = nv0 >= 1.0f, s1 = nv1 >= 1.0f;
            v0 = s0 ? 0.0f : nv0;
            v1 = s1 ? 0.0f : nv1;
            if (t == 127) { out0 = s0 ? 1.0f : 0.0f; out1 = s1 ? 1.0f : 0.0f; }
            cur = t;
        }
        // no event at t=127  ->  step 127 is pure decay -> no spike -> out stays 0
    } else {
        // dense fallback (bias != 0 or event overflow) — same math as passing kernel
        float v0 = 0.0f, v1 = 0.0f;
        for (int t = 0; t < LEN; ++t) {
            float z0 = bias0, z1 = bias1;
            #pragma unroll
            for (int wq = 0; wq < 8; ++wq) {
                unsigned m = smask[t*8 + wq];
                while (m) {
                    int bit = __ffs(m) - 1; m &= m - 1;
                    const float* wr = g_wt + (wq*32 + bit) * HID;
                    z0 += wr[tid];
                    z1 += wr[tid + 128];
                }
            }
            float nv0 = fmaf(z0 - v0, 0.5f, v0);
            float nv1 = fmaf(z1 - v1, 0.5f, v1);
            bool s0 = nv0 >= 1.0f, s1 = nv1 >= 1.0f;
            v0 = s0 ? 0.0f : nv0;
            v1 = s1 ? 0.0f : nv1;
            if (t == LEN - 1) { out0 = s0 ? 1.0f : 0.0f; out1 = s1 ? 1.0f : 0.0f; }
        }
    }

    const int idx = n * HID + tid;
    for (int cpy = 0; cpy < ncopy; ++cpy) {
        out[cpy*OUT1 + idx]       = out0;
        out[cpy*OUT1 + idx + 128] = out1;
    }
}

// ---------------------------------------------------------------------------
extern "C" void kernel_launch(void* const* d_in, const int* in_sizes, int n_in,
                              void* d_out, int out_size) {
    const float* x     = (const float*)d_in[0];
    const float* convw = (const float*)d_in[1];
    const float* convb = (const float*)d_in[2];
    const float* gamma = (const float*)d_in[3];
    const float* beta  = (const float*)d_in[4];
    const float* mean  = (const float*)d_in[5];
    const float* var   = (const float*)d_in[6];
    const float* linw  = (const float*)d_in[7];
    const float* linb  = (const float*)d_in[8];
    float* out = (float*)d_out;

    int ncopy = out_size / OUT1;
    if (ncopy < 1) ncopy = 1;

    prep_kernel<<<64, 256>>>(convw, convb, gamma, beta, mean, var, linw);
    fused_kernel<<<NROW, 128>>>(x, linb, out, ncopy);
}

// round 14
// speedup vs baseline: 1.0026x; 1.0026x over previous
#include <cuda_runtime.h>
#include <cstdint>

#define BS   64
#define LEN  128
#define CN   32
#define HID  256
#define NROW (BS*CN)          // 2048 sequence rows
#define OUT1 (NROW*HID)       // 524288 output elements per copy
#define EV_CAP 1536           // per-row spike-event capacity (expect ~17)

// Scratch (static __device__ arrays: allocation-free)
__device__ float4 g_coef[HID];        // folded conv+BN coefficients
__device__ float  g_wt[HID*HID];      // Wt[o*256+j] = lin_w[j*256+o]

// ---------------------------------------------------------------------------
// prep: coalesced 32x32 tile transpose of lin_w + conv/BN coefficient fold.
// grid = 64 (8x8 tiles), block = 256 (32x8).
// ---------------------------------------------------------------------------
__global__ void prep_kernel(const float* __restrict__ conv_w,
                            const float* __restrict__ conv_b,
                            const float* __restrict__ bn_gamma,
                            const float* __restrict__ bn_beta,
                            const float* __restrict__ bn_mean,
                            const float* __restrict__ bn_var,
                            const float* __restrict__ lin_w) {
    __shared__ float tile[32][33];
    int bx = blockIdx.x & 7;         // o-tile
    int by = blockIdx.x >> 3;        // j-tile
    int tx = threadIdx.x & 31;
    int ty = threadIdx.x >> 5;       // 0..7

    #pragma unroll
    for (int k = 0; k < 4; ++k) {
        int lj = ty + k * 8;
        tile[lj][tx] = lin_w[(by*32 + lj) * HID + bx*32 + tx];   // coalesced read
    }
    __syncthreads();
    #pragma unroll
    for (int k = 0; k < 4; ++k) {
        int lo = ty + k * 8;
        g_wt[(bx*32 + lo) * HID + by*32 + tx] = tile[tx][lo];    // coalesced write
    }

    if (blockIdx.x == 0) {
        int j = threadIdx.x;         // 0..255
        float inv = bn_gamma[j] / sqrtf(bn_var[j] + 1e-5f);
        float4 cf;
        cf.x = conv_w[j*3 + 0] * inv;
        cf.y = conv_w[j*3 + 1] * inv;
        cf.z = conv_w[j*3 + 2] * inv;
        cf.w = (conv_b[j] - bn_mean[j]) * inv + bn_beta[j];
        g_coef[j] = cf;
    }
}

// ---------------------------------------------------------------------------
// fused encoder + event-driven RNN. grid = NROW (2048), block = 128.
// Phase A: thread l scans LIF over 256 hidden channels for position (b,c,l),
//          masks -> smem.
// Phase B: cooperative build of a time-ordered spike-event list (t,o).
// Phase C: each thread owns neurons j=tid and j=tid+128; skip zero-input
//          steps via exact power-of-2 decay; LIF update only at event steps.
//          Dense fallback if bias != 0 or event overflow.
// ---------------------------------------------------------------------------
__global__ __launch_bounds__(128) void fused_kernel(const float* __restrict__ x,
                                                    const float* __restrict__ lin_b,
                                                    float* __restrict__ out, int ncopy) {
    __shared__ float4   scoef[HID];        // 4KB
    __shared__ unsigned smask[LEN*8];      // 4KB: word i = t*8+w
    __shared__ unsigned sev[EV_CAP];       // 6KB: (t<<8)|o, ordered (t asc, o asc)
    __shared__ int      swcnt[5];

    const int tid  = threadIdx.x;
    const int lane = tid & 31;
    const int wid  = tid >> 5;
    const int n    = blockIdx.x;
    const int b    = n >> 5;
    const int c    = n & 31;

    scoef[tid]       = g_coef[tid];
    scoef[tid + 128] = g_coef[tid + 128];
    float bias0 = lin_b[tid];
    float bias1 = lin_b[tid + 128];
    int anybias = __syncthreads_or(bias0 != 0.0f || bias1 != 0.0f);  // also barriers scoef

    // ---- Phase A: encoder LIF scan over hidden axis (exact arithmetic) ----
    {
        const int l = tid;                       // 0..127
        const int g = b * 4096 + l * 32 + c;     // x flat index (bs, len, c)
        float x0 = x[g];
        float xm = (l > 0)   ? x[g - 32] : 0.0f;
        float xp = (l < 127) ? x[g + 32] : 0.0f;

        float v = 0.0f;
        for (int w = 0; w < 8; ++w) {
            unsigned m = 0;
            #pragma unroll
            for (int bit = 0; bit < 32; ++bit) {
                float4 cf = scoef[w*32 + bit];
                float enc = cf.w;
                enc = fmaf(cf.x, xm, enc);
                enc = fmaf(cf.y, x0, enc);
                enc = fmaf(cf.z, xp, enc);
                v = fmaf(enc - v, 0.5f, v);                       // v += (enc-v)/2
                if (v >= 1.0f) { m |= (1u << bit); v = 0.0f; }    // spike + reset
            }
            smask[l*8 + w] = m;
        }
    }
    __syncthreads();

    // ---- Phase B: build ordered event list (4 warps, 256 words each) ----
    int cnt = 0;
    #pragma unroll
    for (int k = 0; k < 8; ++k)
        cnt += __popc(smask[wid*256 + k*32 + lane]);
    #pragma unroll
    for (int o = 16; o; o >>= 1) cnt += __shfl_down_sync(~0u, cnt, o);
    if (lane == 0) swcnt[wid] = cnt;
    __syncthreads();
    if (tid == 0) {
        int s = 0;
        #pragma unroll
        for (int w = 0; w < 4; ++w) { int t = swcnt[w]; swcnt[w] = s; s += t; }
        swcnt[4] = s;
    }
    __syncthreads();
    const int nev = swcnt[4];
    const bool dense = anybias || (nev > EV_CAP);

    if (!dense) {
        int base = swcnt[wid];
        #pragma unroll
        for (int k = 0; k < 8; ++k) {
            int wi = wid*256 + k*32 + lane;          // word index = t*8 + w
            unsigned word = smask[wi];
            int pc = __popc(word);
            int off = pc;                            // inclusive scan
            #pragma unroll
            for (int o = 1; o < 32; o <<= 1) {
                int t = __shfl_up_sync(~0u, off, o);
                if (lane >= o) off += t;
            }
            int pos = base + off - pc;
            int t  = wi >> 3;
            int wq = wi & 7;
            while (word) {
                int bit = __ffs(word) - 1; word &= word - 1;
                sev[pos++] = (unsigned)((t << 8) | (wq*32 + bit));
            }
            base += __shfl_sync(~0u, off, 31);
        }
    }
    __syncthreads();

    // ---- Phase C: RNN over time ----
    float out0 = 0.0f, out1 = 0.0f;

    if (!dense) {
        float v0 = 0.0f, v1 = 0.0f;
        int cur = -1;
        int e = 0;
        while (e < nev) {
            unsigned ev = sev[e];
            int t = (int)(ev >> 8);
            int gap = t - cur - 1;                       // decay-only steps
            float sc = __int_as_float((127 - gap) << 23); // exact 2^-gap
            v0 *= sc; v1 *= sc;
            float z0 = 0.0f, z1 = 0.0f;
            do {                                          // gather column sums, o asc
                int o = (int)(ev & 255);
                const float* wr = g_wt + o * HID;
                z0 += wr[tid];
                z1 += wr[tid + 128];
                ++e;
                if (e >= nev) break;
                ev = sev[e];
            } while ((int)(ev >> 8) == t);
            float nv0 = fmaf(z0 - v0, 0.5f, v0);
            float nv1 = fmaf(z1 - v1, 0.5f, v1);
            bool s0 = nv0 >= 1.0f, s1 = nv1 >= 1.0f;
            v0 = s0 ? 0.0f : nv0;
            v1 = s1 ? 0.0f : nv1;
            if (t == 127) { out0 = s0 ? 1.0f : 0.0f; out1 = s1 ? 1.0f : 0.0f; }
            cur = t;
        }
        // no event at t=127  ->  step 127 is pure decay -> no spike -> out stays 0
    } else {
        // dense fallback (bias != 0 or event overflow) — same math as passing kernel
        float v0 = 0.0f, v1 = 0.0f;
        for (int t = 0; t < LEN; ++t) {
            float z0 = bias0, z1 = bias1;
            #pragma unroll
            for (int wq = 0; wq < 8; ++wq) {
                unsigned m = smask[t*8 + wq];
                while (m) {
                    int bit = __ffs(m) - 1; m &= m - 1;
                    const float* wr = g_wt + (wq*32 + bit) * HID;
                    z0 += wr[tid];
                    z1 += wr[tid + 128];
                }
            }
            float nv0 = fmaf(z0 - v0, 0.5f, v0);
            float nv1 = fmaf(z1 - v1, 0.5f, v1);
            bool s0 = nv0 >= 1.0f, s1 = nv1 >= 1.0f;
            v0 = s0 ? 0.0f : nv0;
            v1 = s1 ? 0.0f : nv1;
            if (t == LEN - 1) { out0 = s0 ? 1.0f : 0.0f; out1 = s1 ? 1.0f : 0.0f; }
        }
    }

    const int idx = n * HID + tid;
    for (int cpy = 0; cpy < ncopy; ++cpy) {
        out[cpy*OUT1 + idx]       = out0;
        out[cpy*OUT1 + idx + 128] = out1;
    }
}

// ---------------------------------------------------------------------------
extern "C" void kernel_launch(void* const* d_in, const int* in_sizes, int n_in,
                              void* d_out, int out_size) {
    const float* x     = (const float*)d_in[0];
    const float* convw = (const float*)d_in[1];
    const float* convb = (const float*)d_in[2];
    const float* gamma = (const float*)d_in[3];
    const float* beta  = (const float*)d_in[4];
    const float* mean  = (const float*)d_in[5];
    const float* var   = (const float*)d_in[6];
    const float* linw  = (const float*)d_in[7];
    const float* linb  = (const float*)d_in[8];
    float* out = (float*)d_out;

    int ncopy = out_size / OUT1;
    if (ncopy < 1) ncopy = 1;

    prep_kernel<<<64, 256>>>(convw, convb, gamma, beta, mean, var, linw);
    fused_kernel<<<NROW, 128>>>(x, linb, out, ncopy);
}